// round 17
// baseline (speedup 1.0000x reference)
#include <cuda_runtime.h>
#include <cuda_bf16.h>
#include <cuda_fp16.h>
#include <math.h>

// Problem dims
#define Tt 16
#define Mm 1024
#define Hh 128
#define ROWS 16384
#define MAXD 128
#define NL_TR 5

// ---------------- scratch ----------------
__device__ __half g_hh[ROWS * 512];
__device__ float g_ss[ROWS * 4];
__device__ float g_sd[ROWS * 4];
__device__ unsigned char g_m[ROWS];
__device__ int g_cnt[ROWS];
__device__ unsigned short g_nbr[ROWS * MAXD];
__device__ float g_xs[ROWS * Hh];
__device__ float g_c[16];
__device__ float g_pe[Tt * Hh];
__device__ __half g_xa[ROWS * Hh];
__device__ __half g_xb[ROWS * Hh];
__device__ __half g_xsh[ROWS * Hh];

#define WTOT 1310720
#define OFF_GAT 0
#define OFF_QKV 327680
#define OFF_WO  573440
#define OFF_FF1 655360
#define OFF_FF2 983040
__device__ __half g_w16[WTOT];

__device__ __forceinline__ unsigned smem_u32(const void* p) {
    unsigned a;
    asm("{ .reg .u64 t; cvta.to.shared.u64 t, %1; cvt.u32.u64 %0, t; }" : "=r"(a) : "l"(p));
    return a;
}
__device__ __forceinline__ void ldmat4(unsigned& r0, unsigned& r1, unsigned& r2, unsigned& r3, unsigned addr) {
    asm volatile("ldmatrix.sync.aligned.m8n8.x4.shared.b16 {%0,%1,%2,%3}, [%4];"
        : "=r"(r0), "=r"(r1), "=r"(r2), "=r"(r3) : "r"(addr));
}
__device__ __forceinline__ void mma16816(float* c, unsigned a0, unsigned a1, unsigned a2, unsigned a3,
                                         unsigned b0, unsigned b1) {
    asm volatile("mma.sync.aligned.m16n8k16.row.col.f32.f16.f16.f32 "
        "{%0,%1,%2,%3}, {%4,%5,%6,%7}, {%8,%9}, {%0,%1,%2,%3};"
        : "+f"(c[0]), "+f"(c[1]), "+f"(c[2]), "+f"(c[3])
        : "r"(a0), "r"(a1), "r"(a2), "r"(a3), "r"(b0), "r"(b1));
}
__device__ __forceinline__ void cpa16(unsigned dst, const void* src) {
    asm volatile("cp.async.ca.shared.global [%0], [%1], 16;" :: "r"(dst), "l"(src));
}
#define CPA_COMMIT() asm volatile("cp.async.commit_group;" ::: "memory")
#define CPA_WAIT1() asm volatile("cp.async.wait_group 1;" ::: "memory")
#define CPA_WAIT0() asm volatile("cp.async.wait_group 0;" ::: "memory")

__device__ __forceinline__ unsigned packh_hi2(float a, float b) {
    __half2 h = __floats2half2_rn(a, b);
    return *(unsigned*)&h;
}

// SMEM pipeline: planes of 128 rows x 32 fp16 (80B stride)
#define TROW 80
#define PBUF (128 * TROW)
#define STAGE (2 * PBUF)
#define P_A 0
#define P_B PBUF
#define GSM_TOTAL 67584

// layer_fused smem regions (NON-OVERLAPPING liveness):
//   pipeline [0, 40960)           -- all phases
//   stQ      [40960, 141312)      -- QKV staging; dead after phase 4 float stage
//   stF      [40960, 174080)      -- FF1 staging (written phase 5, after stQ dead)
//   stO      [174080, 208896)     -- attn out / LN1 out; live phases 2..5, disjoint
#define LSM_QKV 40960
#define QROW 392
#define LSM_F 40960
#define AROW 520
#define LSM_O 174080
#define OROW 136
#define LSM_TOTAL 208896

// ---------------- HMMA GEMM (GAT projection) ----------------
template <int ACT, bool SCORES>
__global__ void __launch_bounds__(256, 2)
gemm_tc(const __half* __restrict__ Ah, const __half* __restrict__ B16,
        __half* __restrict__ H16,
        const float* __restrict__ asrc, const float* __restrict__ adst,
        float* __restrict__ gss, float* __restrict__ gsd, int Nt, int Kt) {
    extern __shared__ char smem[];
    const unsigned sb = smem_u32(smem);
    const int tid = threadIdx.x;
    const int wid = tid >> 5, lane = tid & 31;
    const int wr = wid >> 1, wc = wid & 1;
    const int row0 = blockIdx.y * 128;
    const int col0 = blockIdx.x * 128;

    float acc[2][8][4];
#pragma unroll
    for (int mt = 0; mt < 2; mt++)
#pragma unroll
        for (int nt = 0; nt < 8; nt++)
#pragma unroll
            for (int e = 0; e < 4; e++) acc[mt][nt][e] = 0.f;

    const int ltile = lane >> 3, lrow = lane & 7;
    const int nch = Kt >> 5;

#define LOAD_CHUNK(cidx, s) do { \
    unsigned base = sb + (s) * STAGE; \
    _Pragma("unroll") \
    for (int j = 0; j < 2; j++) { \
        int i = tid + j * 256; \
        int rr = i >> 2, qq = i & 3; \
        unsigned off = (unsigned)(rr * TROW + qq * 16); \
        cpa16(base + P_A + off, Ah + (size_t)(row0 + rr) * Kt + (cidx) * 32 + qq * 8); \
        cpa16(base + P_B + off, B16 + (size_t)(col0 + rr) * Kt + (cidx) * 32 + qq * 8); \
    } \
} while (0)

    LOAD_CHUNK(0, 0);
    CPA_COMMIT();
    for (int c = 0; c < nch; c++) {
        if (c + 1 < nch) { LOAD_CHUNK(c + 1, (c + 1) & 1); CPA_COMMIT(); CPA_WAIT1(); }
        else CPA_WAIT0();
        __syncthreads();
        unsigned base = sb + (c & 1) * STAGE;
#pragma unroll
        for (int ks = 0; ks < 2; ks++) {
            unsigned ah[2][4];
#pragma unroll
            for (int mt = 0; mt < 2; mt++) {
                int row = wr * 32 + mt * 16 + lrow + (ltile & 1) * 8;
                int kcol = ks * 16 + (ltile >> 1) * 8;
                ldmat4(ah[mt][0], ah[mt][1], ah[mt][2], ah[mt][3],
                       base + P_A + (unsigned)(row * TROW + kcol * 2));
            }
#pragma unroll
            for (int g = 0; g < 4; g++) {
                int n = wc * 64 + g * 16 + lrow + (ltile >> 1) * 8;
                int kcol = ks * 16 + (ltile & 1) * 8;
                unsigned bh[4];
                ldmat4(bh[0], bh[1], bh[2], bh[3],
                       base + P_B + (unsigned)(n * TROW + kcol * 2));
#pragma unroll
                for (int mt = 0; mt < 2; mt++)
#pragma unroll
                    for (int half = 0; half < 2; half++)
                        mma16816(acc[mt][g * 2 + half],
                                 ah[mt][0], ah[mt][1], ah[mt][2], ah[mt][3],
                                 bh[half * 2], bh[half * 2 + 1]);
            }
        }
        __syncthreads();
    }
#undef LOAD_CHUNK

    float* stage = (float*)smem;
#pragma unroll
    for (int mt = 0; mt < 2; mt++)
#pragma unroll
        for (int nt = 0; nt < 8; nt++) {
            int row = wr * 32 + mt * 16 + (lane >> 2);
            int col = wc * 64 + nt * 8 + (lane & 3) * 2;
            *(float2*)(stage + (size_t)row * 132 + col) = make_float2(acc[mt][nt][0], acc[mt][nt][1]);
            *(float2*)(stage + (size_t)(row + 8) * 132 + col) = make_float2(acc[mt][nt][2], acc[mt][nt][3]);
        }
    __syncthreads();

    for (int i = tid; i < 128 * 32; i += 256) {
        int r = i >> 5, q = i & 31;
        int c = q * 4;
        float4 v = *(float4*)(stage + (size_t)r * 132 + c);
        uint2 u;
        u.x = packh_hi2(v.x, v.y);
        u.y = packh_hi2(v.z, v.w);
        *(uint2*)(H16 + (size_t)(row0 + r) * Nt + col0 + c) = u;
    }

    if (SCORES && tid < 128) {
        int r = tid;
        float s1 = 0.f, s2 = 0.f;
        const float* as = asrc + col0;
        const float* ad = adst + col0;
        const float* sp = stage + (size_t)r * 132;
#pragma unroll 8
        for (int c = 0; c < 128; c++) {
            float hv = sp[c];
            s1 += hv * as[c];
            s2 += hv * ad[c];
        }
        gss[(size_t)(row0 + r) * 4 + blockIdx.x] = s1;
        gsd[(size_t)(row0 + r) * 4 + blockIdx.x] = s2;
    }
}

// ---------------- fully fused transformer layer ----------------
template <bool LAST>
__global__ void __launch_bounds__(256, 1)
layer_fused(const __half* __restrict__ Ah,
            const __half* __restrict__ Wqkv16, const float* __restrict__ bqkv,
            const __half* __restrict__ Wo16, const float* __restrict__ bo,
            const float* __restrict__ l1s, const float* __restrict__ l1b,
            const __half* __restrict__ W1, const float* __restrict__ b1,
            const __half* __restrict__ W2, const float* __restrict__ b2,
            const float* __restrict__ l2s, const float* __restrict__ l2b,
            float* __restrict__ xs, __half* __restrict__ xsh_out,
            float* __restrict__ outp) {
    extern __shared__ char smem[];
    const unsigned sb = smem_u32(smem);
    __half* stQ = (__half*)(smem + LSM_QKV);
    __half* stO = (__half*)(smem + LSM_O);
    const unsigned so = sb + LSM_O;
    __half* stF = (__half*)(smem + LSM_F);
    const unsigned sf = sb + LSM_F;
    const int tid = threadIdx.x;
    const int wid = tid >> 5, lane = tid & 31;
    const int wr = wid >> 1, wc = wid & 1;
    const int row0 = blockIdx.x * 128;
    const int ltile = lane >> 3, lrow = lane & 7;

    float acc[2][8][4];

    // ===== Phase 1: QKV GEMM =====
    for (int ct = 0; ct < 3; ct++) {
#pragma unroll
        for (int mt = 0; mt < 2; mt++)
#pragma unroll
            for (int nt = 0; nt < 8; nt++)
#pragma unroll
                for (int e = 0; e < 4; e++) acc[mt][nt][e] = 0.f;

#define LOADQ(cidx, s) do { \
    unsigned base = sb + (s) * STAGE; \
    _Pragma("unroll") \
    for (int j = 0; j < 2; j++) { \
        int i = tid + j * 256; \
        int rr = i >> 2, qq = i & 3; \
        unsigned off = (unsigned)(rr * TROW + qq * 16); \
        cpa16(base + P_A + off, Ah + (size_t)(row0 + rr) * 128 + (cidx) * 32 + qq * 8); \
        cpa16(base + P_B + off, Wqkv16 + (size_t)(ct * 128 + rr) * 128 + (cidx) * 32 + qq * 8); \
    } \
} while (0)
        LOADQ(0, 0);
        CPA_COMMIT();
        for (int c = 0; c < 4; c++) {
            if (c + 1 < 4) { LOADQ(c + 1, (c + 1) & 1); CPA_COMMIT(); CPA_WAIT1(); }
            else CPA_WAIT0();
            __syncthreads();
            unsigned base = sb + (c & 1) * STAGE;
#pragma unroll
            for (int ks = 0; ks < 2; ks++) {
                unsigned ah[2][4];
#pragma unroll
                for (int mt = 0; mt < 2; mt++) {
                    int row = wr * 32 + mt * 16 + lrow + (ltile & 1) * 8;
                    int kcol = ks * 16 + (ltile >> 1) * 8;
                    ldmat4(ah[mt][0], ah[mt][1], ah[mt][2], ah[mt][3],
                           base + P_A + (unsigned)(row * TROW + kcol * 2));
                }
#pragma unroll
                for (int g = 0; g < 4; g++) {
                    int n = wc * 64 + g * 16 + lrow + (ltile >> 1) * 8;
                    int kcol = ks * 16 + (ltile & 1) * 8;
                    unsigned bh[4];
                    ldmat4(bh[0], bh[1], bh[2], bh[3],
                           base + P_B + (unsigned)(n * TROW + kcol * 2));
#pragma unroll
                    for (int mt = 0; mt < 2; mt++)
#pragma unroll
                        for (int half = 0; half < 2; half++)
                            mma16816(acc[mt][g * 2 + half],
                                     ah[mt][0], ah[mt][1], ah[mt][2], ah[mt][3],
                                     bh[half * 2], bh[half * 2 + 1]);
                }
            }
            __syncthreads();
        }
#undef LOADQ
#pragma unroll
        for (int mt = 0; mt < 2; mt++)
#pragma unroll
            for (int nt = 0; nt < 8; nt++) {
                int row = wr * 32 + mt * 16 + (lane >> 2);
                int colt = wc * 64 + nt * 8 + (lane & 3) * 2;
                int col = ct * 128 + colt;
                float bx = bqkv[col], by = bqkv[col + 1];
                *(unsigned*)(stQ + (size_t)row * QROW + col) =
                    packh_hi2(acc[mt][nt][0] + bx, acc[mt][nt][1] + by);
                *(unsigned*)(stQ + (size_t)(row + 8) * QROW + col) =
                    packh_hi2(acc[mt][nt][2] + bx, acc[mt][nt][3] + by);
            }
        __syncthreads();
    }

    // ===== Phase 2: attention (8 sequences, 2 at a time) =====
    {
        int sl2 = tid >> 7;
        int t2 = tid & 127;
        int h = t2 >> 5;
        int tq = (t2 >> 1) & 15;
        int half = t2 & 1;
        const float scale = 0.17677669529663687f;
        for (int p = 0; p < 4; p++) {
            int sl = p * 2 + sl2;
            const __half* qb = stQ + (size_t)(sl * 16) * QROW;
            float sc[16];
            float mx = -1e30f;
#pragma unroll
            for (int tk = 0; tk < 16; tk++) {
                float s = 0.f;
                const __half* qr = qb + (size_t)tq * QROW + h * 32 + half * 16;
                const __half* kr = qb + (size_t)tk * QROW + 128 + h * 32 + half * 16;
#pragma unroll
                for (int dd = 0; dd < 16; dd++)
                    s += __half2float(qr[dd]) * __half2float(kr[dd]);
                s += __shfl_xor_sync(0xFFFFFFFFu, s, 1);
                s *= scale;
                sc[tk] = s;
                mx = fmaxf(mx, s);
            }
            float sum = 0.f;
#pragma unroll
            for (int tk = 0; tk < 16; tk++) { sc[tk] = expf(sc[tk] - mx); sum += sc[tk]; }
            float inv = 1.f / sum;
            __half* orow = stO + (size_t)(sl * 16 + tq) * OROW + h * 32 + half * 16;
#pragma unroll
            for (int dd = 0; dd < 16; dd++) {
                float o = 0.f;
                const __half* vcol = qb + 256 + h * 32 + half * 16 + dd;
#pragma unroll
                for (int tk = 0; tk < 16; tk++)
                    o += sc[tk] * __half2float(vcol[(size_t)tk * QROW]);
                orow[dd] = __float2half_rn(o * inv);
            }
        }
    }
    __syncthreads();

    // ===== Phase 3: Wo GEMM (A from stO, B pipelined) =====
#pragma unroll
    for (int mt = 0; mt < 2; mt++)
#pragma unroll
        for (int nt = 0; nt < 8; nt++)
#pragma unroll
            for (int e = 0; e < 4; e++) acc[mt][nt][e] = 0.f;

#define LOADB(W, KT, cidx, s) do { \
    unsigned base = sb + (s) * PBUF; \
    _Pragma("unroll") \
    for (int j = 0; j < 2; j++) { \
        int i = tid + j * 256; \
        int rr = i >> 2, qq = i & 3; \
        cpa16(base + (unsigned)(rr * TROW + qq * 16), \
              (W) + (size_t)rr * (KT) + (cidx) * 32 + qq * 8); \
    } \
} while (0)
    LOADB(Wo16, 128, 0, 0);
    CPA_COMMIT();
    for (int c = 0; c < 4; c++) {
        if (c + 1 < 4) { LOADB(Wo16, 128, c + 1, (c + 1) & 1); CPA_COMMIT(); CPA_WAIT1(); }
        else CPA_WAIT0();
        __syncthreads();
        unsigned base = sb + (c & 1) * PBUF;
#pragma unroll
        for (int ks = 0; ks < 2; ks++) {
            unsigned ah[2][4];
#pragma unroll
            for (int mt = 0; mt < 2; mt++) {
                int row = wr * 32 + mt * 16 + lrow + (ltile & 1) * 8;
                int kcol = c * 32 + ks * 16 + (ltile >> 1) * 8;
                ldmat4(ah[mt][0], ah[mt][1], ah[mt][2], ah[mt][3],
                       so + (unsigned)(row * (OROW * 2) + kcol * 2));
            }
#pragma unroll
            for (int g = 0; g < 4; g++) {
                int n = wc * 64 + g * 16 + lrow + (ltile >> 1) * 8;
                int kcol = ks * 16 + (ltile & 1) * 8;
                unsigned bh[4];
                ldmat4(bh[0], bh[1], bh[2], bh[3],
                       base + (unsigned)(n * TROW + kcol * 2));
#pragma unroll
                for (int mt = 0; mt < 2; mt++)
#pragma unroll
                    for (int half = 0; half < 2; half++)
                        mma16816(acc[mt][g * 2 + half],
                                 ah[mt][0], ah[mt][1], ah[mt][2], ah[mt][3],
                                 bh[half * 2], bh[half * 2 + 1]);
            }
        }
        __syncthreads();
    }

    // ===== Phase 4: Wo epilogue — bias + resid + LN1; fp32 -> xs, fp16 -> stO =====
    {
        float* stage = (float*)stQ;
#pragma unroll
        for (int mt = 0; mt < 2; mt++)
#pragma unroll
            for (int nt = 0; nt < 8; nt++) {
                int row = wr * 32 + mt * 16 + (lane >> 2);
                int col = wc * 64 + nt * 8 + (lane & 3) * 2;
                *(float2*)(stage + (size_t)row * 132 + col) = make_float2(acc[mt][nt][0], acc[mt][nt][1]);
                *(float2*)(stage + (size_t)(row + 8) * 132 + col) = make_float2(acc[mt][nt][2], acc[mt][nt][3]);
            }
        __syncthreads();
        const int c = lane * 4;
        float4 bb = *(const float4*)(bo + c);
        float4 sv = *(const float4*)(l1s + c);
        float4 bv = *(const float4*)(l1b + c);
#pragma unroll 4
        for (int rr = 0; rr < 16; rr++) {
            int r = wid * 16 + rr;
            float4 v = *(float4*)(stage + (size_t)r * 132 + c);
            float4 res = *(const float4*)(xs + (size_t)(row0 + r) * 128 + c);
            v.x += bb.x + res.x; v.y += bb.y + res.y;
            v.z += bb.z + res.z; v.w += bb.w + res.w;
            float s = v.x + v.y + v.z + v.w;
#pragma unroll
            for (int o = 16; o; o >>= 1) s += __shfl_xor_sync(0xFFFFFFFFu, s, o);
            float mean = s * (1.f / 128.f);
            float dx = v.x - mean, dy = v.y - mean, dz = v.z - mean, dw = v.w - mean;
            float qq = dx * dx + dy * dy + dz * dz + dw * dw;
#pragma unroll
            for (int o = 16; o; o >>= 1) qq += __shfl_xor_sync(0xFFFFFFFFu, qq, o);
            float rstd = rsqrtf(qq * (1.f / 128.f) + 1e-5f);
            float4 ov;
            ov.x = dx * rstd * sv.x + bv.x;
            ov.y = dy * rstd * sv.y + bv.y;
            ov.z = dz * rstd * sv.z + bv.z;
            ov.w = dw * rstd * sv.w + bv.w;
            *(float4*)(xs + (size_t)(row0 + r) * 128 + c) = ov;
            uint2 uh;
            uh.x = packh_hi2(ov.x, ov.y); uh.y = packh_hi2(ov.z, ov.w);
            *(uint2*)(stO + (size_t)r * OROW + c) = uh;
        }
    }
    __syncthreads();

    // ===== Phase 5: FF1 (A from stO, B pipelined) -> stF =====
    for (int ct = 0; ct < 4; ct++) {
#pragma unroll
        for (int mt = 0; mt < 2; mt++)
#pragma unroll
            for (int nt = 0; nt < 8; nt++)
#pragma unroll
                for (int e = 0; e < 4; e++) acc[mt][nt][e] = 0.f;

        LOADB(W1 + (size_t)ct * 128 * 128, 128, 0, 0);
        CPA_COMMIT();
        for (int c = 0; c < 4; c++) {
            if (c + 1 < 4) { LOADB(W1 + (size_t)ct * 128 * 128, 128, c + 1, (c + 1) & 1); CPA_COMMIT(); CPA_WAIT1(); }
            else CPA_WAIT0();
            __syncthreads();
            unsigned base = sb + (c & 1) * PBUF;
#pragma unroll
            for (int ks = 0; ks < 2; ks++) {
                unsigned ah[2][4];
#pragma unroll
                for (int mt = 0; mt < 2; mt++) {
                    int row = wr * 32 + mt * 16 + lrow + (ltile & 1) * 8;
                    int kcol = c * 32 + ks * 16 + (ltile >> 1) * 8;
                    ldmat4(ah[mt][0], ah[mt][1], ah[mt][2], ah[mt][3],
                           so + (unsigned)(row * (OROW * 2) + kcol * 2));
                }
#pragma unroll
                for (int g = 0; g < 4; g++) {
                    int n = wc * 64 + g * 16 + lrow + (ltile >> 1) * 8;
                    int kcol = ks * 16 + (ltile & 1) * 8;
                    unsigned bh[4];
                    ldmat4(bh[0], bh[1], bh[2], bh[3],
                           base + (unsigned)(n * TROW + kcol * 2));
#pragma unroll
                    for (int mt = 0; mt < 2; mt++)
#pragma unroll
                        for (int half = 0; half < 2; half++)
                            mma16816(acc[mt][g * 2 + half],
                                     ah[mt][0], ah[mt][1], ah[mt][2], ah[mt][3],
                                     bh[half * 2], bh[half * 2 + 1]);
                }
            }
            __syncthreads();
        }
#pragma unroll
        for (int mt = 0; mt < 2; mt++)
#pragma unroll
            for (int nt = 0; nt < 8; nt++) {
                int row = wr * 32 + mt * 16 + (lane >> 2);
                int colt = wc * 64 + nt * 8 + (lane & 3) * 2;
                int col = ct * 128 + colt;
                float bx = b1[col], by = b1[col + 1];
                float v0 = fmaxf(acc[mt][nt][0] + bx, 0.f);
                float v1 = fmaxf(acc[mt][nt][1] + by, 0.f);
                float v2 = fmaxf(acc[mt][nt][2] + bx, 0.f);
                float v3 = fmaxf(acc[mt][nt][3] + by, 0.f);
                *(unsigned*)(stF + (size_t)row * AROW + col) = packh_hi2(v0, v1);
                *(unsigned*)(stF + (size_t)(row + 8) * AROW + col) = packh_hi2(v2, v3);
            }
        __syncthreads();
    }

    // ===== Phase 6: FF2 (A from stF, B pipelined, K=512) =====
#pragma unroll
    for (int mt = 0; mt < 2; mt++)
#pragma unroll
        for (int nt = 0; nt < 8; nt++)
#pragma unroll
            for (int e = 0; e < 4; e++) acc[mt][nt][e] = 0.f;

    LOADB(W2, 512, 0, 0);
    CPA_COMMIT();
    for (int c = 0; c < 16; c++) {
        if (c + 1 < 16) { LOADB(W2, 512, c + 1, (c + 1) & 1); CPA_COMMIT(); CPA_WAIT1(); }
        else CPA_WAIT0();
        __syncthreads();
        unsigned base = sb + (c & 1) * PBUF;
#pragma unroll
        for (int ks = 0; ks < 2; ks++) {
            unsigned ah[2][4];
#pragma unroll
            for (int mt = 0; mt < 2; mt++) {
                int row = wr * 32 + mt * 16 + lrow + (ltile & 1) * 8;
                int kcol = c * 32 + ks * 16 + (ltile >> 1) * 8;
                ldmat4(ah[mt][0], ah[mt][1], ah[mt][2], ah[mt][3],
                       sf + (unsigned)(row * (AROW * 2) + kcol * 2));
            }
#pragma unroll
            for (int g = 0; g < 4; g++) {
                int n = wc * 64 + g * 16 + lrow + (ltile >> 1) * 8;
                int kcol = ks * 16 + (ltile & 1) * 8;
                unsigned bh[4];
                ldmat4(bh[0], bh[1], bh[2], bh[3],
                       base + (unsigned)(n * TROW + kcol * 2));
#pragma unroll
                for (int mt = 0; mt < 2; mt++)
#pragma unroll
                    for (int half = 0; half < 2; half++)
                        mma16816(acc[mt][g * 2 + half],
                                 ah[mt][0], ah[mt][1], ah[mt][2], ah[mt][3],
                                 bh[half * 2], bh[half * 2 + 1]);
            }
        }
        __syncthreads();
    }
#undef LOADB

    // ===== Phase 7: FF2 epilogue — bias + resid + LN2 =====
    {
        float* stage = (float*)stF;
        __syncthreads();
#pragma unroll
        for (int mt = 0; mt < 2; mt++)
#pragma unroll
            for (int nt = 0; nt < 8; nt++) {
                int row = wr * 32 + mt * 16 + (lane >> 2);
                int col = wc * 64 + nt * 8 + (lane & 3) * 2;
                *(float2*)(stage + (size_t)row * 132 + col) = make_float2(acc[mt][nt][0], acc[mt][nt][1]);
                *(float2*)(stage + (size_t)(row + 8) * 132 + col) = make_float2(acc[mt][nt][2], acc[mt][nt][3]);
            }
        __syncthreads();
        const int c = lane * 4;
        float4 bb = *(const float4*)(b2 + c);
        float4 sv = *(const float4*)(l2s + c);
        float4 bv = *(const float4*)(l2b + c);
#pragma unroll 4
        for (int rr = 0; rr < 16; rr++) {
            int r = wid * 16 + rr;
            float4 v = *(float4*)(stage + (size_t)r * 132 + c);
            float4 res = *(const float4*)(xs + (size_t)(row0 + r) * 128 + c);
            v.x += bb.x + res.x; v.y += bb.y + res.y;
            v.z += bb.z + res.z; v.w += bb.w + res.w;
            float s = v.x + v.y + v.z + v.w;
#pragma unroll
            for (int o = 16; o; o >>= 1) s += __shfl_xor_sync(0xFFFFFFFFu, s, o);
            float mean = s * (1.f / 128.f);
            float dx = v.x - mean, dy = v.y - mean, dz = v.z - mean, dw = v.w - mean;
            float qq = dx * dx + dy * dy + dz * dz + dw * dw;
#pragma unroll
            for (int o = 16; o; o >>= 1) qq += __shfl_xor_sync(0xFFFFFFFFu, qq, o);
            float rstd = rsqrtf(qq * (1.f / 128.f) + 1e-5f);
            float4 ov;
            ov.x = dx * rstd * sv.x + bv.x;
            ov.y = dy * rstd * sv.y + bv.y;
            ov.z = dz * rstd * sv.z + bv.z;
            ov.w = dw * rstd * sv.w + bv.w;
            if (LAST) {
                *(float4*)(outp + (size_t)(row0 + r) * 128 + c) = ov;
            } else {
                *(float4*)(xs + (size_t)(row0 + r) * 128 + c) = ov;
                uint2 uh;
                uh.x = packh_hi2(ov.x, ov.y); uh.y = packh_hi2(ov.z, ov.w);
                *(uint2*)(xsh_out + (size_t)(row0 + r) * 128 + c) = uh;
            }
        }
    }
}

// ---------------- weight conversion ----------------
__global__ void split_weights(const float* __restrict__ gatW, const float* __restrict__ Wqkv,
                              const float* __restrict__ Wo, const float* __restrict__ Wff1,
                              const float* __restrict__ Wff2) {
    int idx = blockIdx.x * 256 + threadIdx.x;
    if (idx >= WTOT) return;
    float v;
    if (idx < OFF_QKV) {
        int i = idx >> 16, r = idx & 65535;
        int n = r >> 7, k = r & 127;
        v = gatW[(i << 16) + k * 512 + n];
    } else if (idx < OFF_WO) {
        int r0 = idx - OFF_QKV;
        int l = r0 / 49152;
        int rem = r0 - l * 49152;
        int n = rem >> 7, k = rem & 127;
        int s = n >> 7, nc = n & 127;
        v = Wqkv[((l * 3 + s) << 14) + k * 128 + nc];
    } else if (idx < OFF_FF1) {
        int r0 = idx - OFF_WO;
        int i = r0 >> 14, r = r0 & 16383;
        int n = r >> 7, k = r & 127;
        v = Wo[(i << 14) + k * 128 + n];
    } else if (idx < OFF_FF2) {
        int r0 = idx - OFF_FF1;
        int i = r0 >> 16, r = r0 & 65535;
        int n = r >> 7, k = r & 127;
        v = Wff1[(i << 16) + k * 512 + n];
    } else {
        int r0 = idx - OFF_FF2;
        int i = r0 >> 16, r = r0 & 65535;
        int n = r >> 9, k = r & 511;
        v = Wff2[(i << 16) + k * 128 + n];
    }
    g_w16[idx] = __float2half_rn(v);
}

// ---------------- tiny precompute ----------------
__global__ void precompute(const float* __restrict__ W, const float* __restrict__ asrc,
                           const float* __restrict__ adst) {
    int tid = threadIdx.x;
    int wid = tid >> 5, lane = tid & 31;
    float a0s = 0.f, a1s = 0.f, a0d = 0.f, a1d = 0.f;
    for (int d = lane; d < 128; d += 32) {
        int c = wid * 128 + d;
        float w0 = W[c], w1 = W[512 + c], as = asrc[c], ad = adst[c];
        a0s += w0 * as; a1s += w1 * as; a0d += w0 * ad; a1d += w1 * ad;
    }
#pragma unroll
    for (int o = 16; o; o >>= 1) {
        a0s += __shfl_xor_sync(0xFFFFFFFFu, a0s, o);
        a1s += __shfl_xor_sync(0xFFFFFFFFu, a1s, o);
        a0d += __shfl_xor_sync(0xFFFFFFFFu, a0d, o);
        a1d += __shfl_xor_sync(0xFFFFFFFFu, a1d, o);
    }
    if (lane == 0) {
        g_c[wid] = a0s; g_c[4 + wid] = a1s; g_c[8 + wid] = a0d; g_c[12 + wid] = a1d;
    }
    for (int i = tid; i < Tt * Hh; i += 128) {
        int t = i >> 7, d = i & 127;
        float freq = expf(-(float)(d & ~1) * (9.210340371976184f / 128.f));
        float ang = (float)t * freq;
        g_pe[i] = (d & 1) ? cosf(ang) : sinf(ang);
    }
}

// ---------------- mask + self-loop init ----------------
__global__ void mask_init(const unsigned char* __restrict__ ego) {
    int idx = blockIdx.x * 256 + threadIdx.x;
    if (idx >= ROWS) return;
    int t = idx >> 10;
    int mm = idx & 1023;
    int b = mm >> 8;
    int n = mm & 255;
    unsigned char v = ego[(b * Tt + t) * 256 + n] ? 1 : 0;
    g_m[idx] = v;
    g_cnt[idx] = v ? 1 : 0;
    g_nbr[idx * MAXD] = (unsigned short)mm;
}

// ---------------- neighbor-list build ----------------
__global__ void build_nbr(const float* __restrict__ A) {
    int tj0 = blockIdx.x * 2;
    int tj1 = tj0 + 1;
    bool m0 = g_m[tj0] != 0, m1 = g_m[tj1] != 0;
    int i0 = threadIdx.x * 4;
    float4 a0, a1;
    if (m0) a0 = *(const float4*)(A + (size_t)tj0 * 1024 + i0);
    if (m1) a1 = *(const float4*)(A + (size_t)tj1 * 1024 + i0);
    if (m0) {
        int t = tj0 >> 10, j = tj0 & 1023;
        float av[4] = {a0.x, a0.y, a0.z, a0.w};
#pragma unroll
        for (int e = 0; e < 4; e++) {
            int i = i0 + e;
            if (i == j) continue;
            int ti = (t << 10) + i;
            if (av[e] != 0.f && g_m[ti]) {
                int pos = atomicAdd(&g_cnt[ti], 1);
                if (pos < MAXD) g_nbr[(size_t)ti * MAXD + pos] = (unsigned short)j;
            }
        }
    }
    if (m1) {
        int t = tj1 >> 10, j = tj1 & 1023;
        float av[4] = {a1.x, a1.y, a1.z, a1.w};
#pragma unroll
        for (int e = 0; e < 4; e++) {
            int i = i0 + e;
            if (i == j) continue;
            int ti = (t << 10) + i;
            if (av[e] != 0.f && g_m[ti]) {
                int pos = atomicAdd(&g_cnt[ti], 1);
                if (pos < MAXD) g_nbr[(size_t)ti * MAXD + pos] = (unsigned short)j;
            }
        }
    }
}

// ---------------- GAT layer-0 ----------------
__global__ void gat0(const float* __restrict__ x, const float* __restrict__ W) {
    int idx = blockIdx.x * 256 + threadIdx.x;
    int row = idx >> 9;
    int c = idx & 511;
    float x0 = x[row * 2], x1 = x[row * 2 + 1];
    g_hh[idx] = __float2half(x0 * W[c] + x1 * W[512 + c]);
    if (c < 8) {
        int hh = c & 3;
        int isd = c >> 2;
        float v = x0 * g_c[hh + isd * 8] + x1 * g_c[hh + 4 + isd * 8];
        if (isd == 0) g_ss[row * 4 + hh] = v;
        else g_sd[row * 4 + hh] = v;
    }
}

// ---------------- sparse segment-softmax + aggregation ----------------
template <bool TOSEQ>
__global__ void gat_agg(const float* __restrict__ bias, __half* __restrict__ xh) {
    int row = blockIdx.x;
    int tid = threadIdx.x;
    int t = row >> 10;
    int mm = row & 1023;
    bool alive = g_m[row] != 0;

    __shared__ unsigned short nb[MAXD];
    __shared__ float w[4][MAXD];
    __shared__ float part[128][9];

    float outv = 0.f;
    if (alive) {
        int cnt = g_cnt[row];
        if (cnt > MAXD) cnt = MAXD;
        if (tid < cnt) nb[tid] = g_nbr[(size_t)row * MAXD + tid];

        if (tid < cnt) {
            int jr = (t << 10) + nb[tid];
#pragma unroll
            for (int hh = 0; hh < 4; hh++) {
                float z = g_sd[row * 4 + hh] + g_ss[jr * 4 + hh];
                w[hh][tid] = (z > 0.f) ? z : 0.2f * z;
            }
        } else {
#pragma unroll
            for (int hh = 0; hh < 4; hh++) w[hh][tid] = -INFINITY;
        }
        __syncthreads();

        {
            int wh = tid >> 5, lane = tid & 31;
            float v0 = w[wh][lane], v1 = w[wh][lane + 32], v2 = w[wh][lane + 64], v3 = w[wh][lane + 96];
            float mx = fmaxf(fmaxf(v0, v1), fmaxf(v2, v3));
#pragma unroll
            for (int o = 16; o; o >>= 1) mx = fmaxf(mx, __shfl_xor_sync(0xFFFFFFFFu, mx, o));
            float e0 = expf(v0 - mx), e1 = expf(v1 - mx), e2 = expf(v2 - mx), e3 = expf(v3 - mx);
            float s = e0 + e1 + e2 + e3;
#pragma unroll
            for (int o = 16; o; o >>= 1) s += __shfl_xor_sync(0xFFFFFFFFu, s, o);
            float inv = 1.f / s;
            w[wh][lane] = e0 * inv;
            w[wh][lane + 32] = e1 * inv;
            w[wh][lane + 64] = e2 * inv;
            w[wh][lane + 96] = e3 * inv;
        }
        __syncthreads();

        int h = (tid >> 4) & 3, dsl = tid & 15, nh = tid >> 6;
        float acc[8];
#pragma unroll
        for (int e = 0; e < 8; e++) acc[e] = 0.f;
        const __half* tb = g_hh + (((size_t)(t << 10)) << 9) + h * 128 + dsl * 8;
        for (int j = nh; j < cnt; j += 2) {
            float wj = w[h][j];
            uint4 q = *(const uint4*)(tb + ((size_t)nb[j] << 9));
            __half2* hp = (__half2*)&q;
#pragma unroll
            for (int e = 0; e < 4; e++) {
                float2 f = __half22float2(hp[e]);
                acc[2 * e] += wj * f.x;
                acc[2 * e + 1] += wj * f.y;
            }
        }
#pragma unroll
        for (int e = 0; e < 8; e++) part[tid][e] = acc[e];
        __syncthreads();

        int dsl2 = tid >> 3, e2 = tid & 7;
        float s = 0.f;
#pragma unroll
        for (int k = 0; k < 8; k++) {
            int c = (k & 1) * 64 + (k >> 1) * 16 + dsl2;
            s += part[c][e2];
        }
        outv = fmaxf(s * 0.25f + bias[tid], 0.f);
    }

    if (TOSEQ) {
        float v = outv + g_pe[t * 128 + tid];
        size_t sidx = ((size_t)mm * Tt + t) * Hh + tid;
        g_xs[sidx] = v;
        g_xsh[sidx] = __float2half_rn(v);
    } else {
        xh[(size_t)row * 128 + tid] = __float2half_rn(outv);
    }
}

// ---------------- launcher ----------------
extern "C" void kernel_launch(void* const* d_in, const int* in_sizes, int n_in,
                              void* d_out, int out_size) {
    const unsigned char* ego = (const unsigned char*)d_in[0];
    const float* positions  = (const float*)d_in[1];
    const float* adjacency  = (const float*)d_in[2];
    const float* gat1_W     = (const float*)d_in[3];
    const float* gat1_asrc  = (const float*)d_in[4];
    const float* gat1_adst  = (const float*)d_in[5];
    const float* gat1_b     = (const float*)d_in[6];
    const float* gatW       = (const float*)d_in[7];
    const float* gat_asrc   = (const float*)d_in[8];
    const float* gat_adst   = (const float*)d_in[9];
    const float* gat_b      = (const float*)d_in[10];
    const float* Wqkv       = (const float*)d_in[11];
    const float* bqkv       = (const float*)d_in[12];
    const float* Wo         = (const float*)d_in[13];
    const float* bo         = (const float*)d_in[14];
    const float* ln1_s      = (const float*)d_in[15];
    const float* ln1_b      = (const float*)d_in[16];
    const float* ln2_s      = (const float*)d_in[17];
    const float* ln2_b      = (const float*)d_in[18];
    const float* Wff1       = (const float*)d_in[19];
    const float* bff1       = (const float*)d_in[20];
    const float* Wff2       = (const float*)d_in[21];
    const float* bff2       = (const float*)d_in[22];
    float* out = (float*)d_out;

    float *xs, *ss, *sd;
    __half *hh, *w16, *xa, *xb, *xsh;
    cudaGetSymbolAddress((void**)&hh,   g_hh);
    cudaGetSymbolAddress((void**)&xs,   g_xs);
    cudaGetSymbolAddress((void**)&ss,   g_ss);
    cudaGetSymbolAddress((void**)&sd,   g_sd);
    cudaGetSymbolAddress((void**)&w16,  g_w16);
    cudaGetSymbolAddress((void**)&xa,   g_xa);
    cudaGetSymbolAddress((void**)&xb,   g_xb);
    cudaGetSymbolAddress((void**)&xsh,  g_xsh);

    cudaFuncSetAttribute(gemm_tc<0, true>,   cudaFuncAttributeMaxDynamicSharedMemorySize, GSM_TOTAL);
    cudaFuncSetAttribute(layer_fused<false>, cudaFuncAttributeMaxDynamicSharedMemorySize, LSM_TOTAL);
    cudaFuncSetAttribute(layer_fused<true>,  cudaFuncAttributeMaxDynamicSharedMemorySize, LSM_TOTAL);

    split_weights<<<(WTOT + 255) / 256, 256>>>(gatW, Wqkv, Wo, Wff1, Wff2);
    precompute<<<1, 128>>>(gat1_W, gat1_asrc, gat1_adst);
    mask_init<<<ROWS / 256, 256>>>(ego);
    build_nbr<<<ROWS / 2, 256>>>(adjacency);

    gat0<<<ROWS * 512 / 256, 256>>>(positions, gat1_W);
    gat_agg<false><<<ROWS, 128>>>(gat1_b, xa);

    __half *cur = xa, *nxt = xb;
    for (int i = 0; i < 5; i++) {
        dim3 gp(4, ROWS / 128);
        gemm_tc<0, true><<<gp, 256, GSM_TOTAL>>>(
            cur, w16 + OFF_GAT + (size_t)i * 65536, hh,
            gat_asrc + i * 512, gat_adst + i * 512, ss, sd, 512, 128);
        if (i < 4) {
            gat_agg<false><<<ROWS, 128>>>(gat_b + i * 128, nxt);
            __half* t0 = cur; cur = nxt; nxt = t0;
        } else {
            gat_agg<true><<<ROWS, 128>>>(gat_b + i * 128, nullptr);
        }
    }

    for (int l = 0; l < NL_TR; l++) {
        size_t oq  = OFF_QKV + (size_t)l * 49152;
        size_t owo = OFF_WO  + (size_t)l * 16384;
        size_t of1 = OFF_FF1 + (size_t)l * 65536;
        size_t of2 = OFF_FF2 + (size_t)l * 65536;
        if (l == NL_TR - 1) {
            layer_fused<true><<<ROWS / 128, 256, LSM_TOTAL>>>(
                xsh, w16 + oq, bqkv + l * 384, w16 + owo, bo + l * 128,
                ln1_s + l * 128, ln1_b + l * 128,
                w16 + of1, bff1 + l * 512, w16 + of2, bff2 + l * 128,
                ln2_s + l * 128, ln2_b + l * 128,
                xs, nullptr, out);
        } else {
            layer_fused<false><<<ROWS / 128, 256, LSM_TOTAL>>>(
                xsh, w16 + oq, bqkv + l * 384, w16 + owo, bo + l * 128,
                ln1_s + l * 128, ln1_b + l * 128,
                w16 + of1, bff1 + l * 512, w16 + of2, bff2 + l * 128,
                ln2_s + l * 128, ln2_b + l * 128,
                xs, xsh, nullptr);
        }
    }
}